// round 9
// baseline (speedup 1.0000x reference)
#include <cuda_runtime.h>
#include <cuda_bf16.h>
#include <math.h>
#include <stdint.h>

// Problem dims
#define BB 2
#define CC 384
#define HH 360
#define WW 720
#define LL 180
#define MM 181
#define NF 362
#define NRr 276480               // BB*CC*HH
#define BCL 138240               // BB*CC*LL
#define NTOT 199065600
#define KE 384                   // padded fold length
#define NP1 192                  // padded m-dim

// ---------------- device globals (allocation-free scratch) -----------------
__device__ __nv_bfloat16 g_Eh[(size_t)NRr * KE];   // even fold hi [row][k]
__device__ __nv_bfloat16 g_El[(size_t)NRr * KE];
__device__ __nv_bfloat16 g_Oh[(size_t)NRr * KE];   // odd fold hi
__device__ __nv_bfloat16 g_Ol[(size_t)NRr * KE];
__device__ __nv_bfloat16 g_Fch[NP1 * KE], g_Fcl[NP1 * KE];   // fwd cos basis [n][k]
__device__ __nv_bfloat16 g_Fsh[NP1 * KE], g_Fsl[NP1 * KE];   // fwd -sin basis [n][k]
__device__ __nv_bfloat16 g_Ich[2 * NP1 * NP1], g_Icl[2 * NP1 * NP1]; // inv cos [j][m]
__device__ __nv_bfloat16 g_Ish[2 * NP1 * NP1], g_Isl[2 * NP1 * NP1]; // inv sin [j][m]
__device__ float g_pctT[(size_t)MM * HH * LL];     // [m][h][l]
__device__ float g_ipctT[(size_t)MM * LL * HH];    // [m][l][h]
__device__ float g_xm[(size_t)(2 * NP1) * NRr];    // [2n+ri][row] fp32
__device__ float g_cf[(size_t)NF * BCL];           // [2m+ri][bc*180+l]
__device__ __nv_bfloat16 g_x2h[(size_t)(2 * NP1) * NRr]; // xm2 hi [plane][row]
__device__ __nv_bfloat16 g_x2l[(size_t)(2 * NP1) * NRr]; // xm2 lo

// ---------------- warp-mma helpers (sm_80+ baseline PTX) --------------------
static __device__ __forceinline__ uint32_t s2u(const void* ptr) {
    uint32_t a;
    asm("{ .reg .u64 t; cvta.to.shared.u64 t, %1; cvt.u32.u64 %0, t; }" : "=r"(a) : "l"(ptr));
    return a;
}
#define LDMX4(r, addr) \
    asm volatile("ldmatrix.sync.aligned.m8n8.x4.shared.b16 {%0,%1,%2,%3}, [%4];" \
        : "=r"((r)[0]), "=r"((r)[1]), "=r"((r)[2]), "=r"((r)[3]) : "r"(addr))
#define LDMX4T(r, addr) \
    asm volatile("ldmatrix.sync.aligned.m8n8.x4.trans.shared.b16 {%0,%1,%2,%3}, [%4];" \
        : "=r"((r)[0]), "=r"((r)[1]), "=r"((r)[2]), "=r"((r)[3]) : "r"(addr))
#define MMA_BF16(d, a, b0v, b1v) \
    asm volatile("mma.sync.aligned.m16n8k16.row.col.f32.bf16.bf16.f32 " \
        "{%0,%1,%2,%3},{%4,%5,%6,%7},{%8,%9},{%0,%1,%2,%3};" \
        : "+f"((d)[0]), "+f"((d)[1]), "+f"((d)[2]), "+f"((d)[3]) \
        : "r"((a)[0]), "r"((a)[1]), "r"((a)[2]), "r"((a)[3]), "r"(b0v), "r"(b1v))

static __device__ __forceinline__ void split2(float v, __nv_bfloat16& h, __nv_bfloat16& l) {
    h = __float2bfloat16(v);
    l = __float2bfloat16(v - __bfloat162float(h));
}

// ---------------- basis builders -------------------------------------------
__global__ void kb_f2() {
    int idx = blockIdx.x * 256 + threadIdx.x;
    if (idx >= NP1 * KE) return;
    int n = idx / KE, k = idx % KE;
    float fc = 0.f, fs = 0.f;
    if (n <= 180) {
        double s, c;
        if (k <= 360) { sincospi((double)(n * k) / 360.0, &s, &c); fc = (float)c; }
        if (k <= 358) { sincospi((double)(n * (k + 1)) / 360.0, &s, &c); fs = (float)(-s); }
    }
    split2(fc, g_Fch[idx], g_Fcl[idx]);
    split2(fs, g_Fsh[idx], g_Fsl[idx]);
}

__global__ void kb_i2() {
    int idx = blockIdx.x * 256 + threadIdx.x;
    if (idx >= 2 * NP1 * NP1) return;
    int j = idx / NP1, m = idx % NP1;
    float ic = 0.f, is = 0.f;
    if (m <= 180 && j <= 360) {
        double sc = (m == 0 ? 1.0 : 2.0) / 720.0;
        double s, c;
        sincospi((double)(m * j) / 360.0, &s, &c);
        ic = (float)(sc * c);
        is = (float)(sc * s);
    }
    split2(ic, g_Ich[idx], g_Icl[idx]);
    split2(is, g_Ish[idx], g_Isl[idx]);
}

// pctT[m][h][l] = pct[h][l][m]
__global__ void kT_pct(const float* __restrict__ pct) {
    size_t idx = (size_t)blockIdx.x * 256 + threadIdx.x;
    if (idx >= (size_t)MM * HH * LL) return;
    int l = (int)(idx % LL);
    size_t t = idx / LL;
    int h = (int)(t % HH);
    int m = (int)(t / HH);
    g_pctT[idx] = pct[((size_t)h * LL + l) * MM + m];
}
// ipctT[m][l][h] = ipct[h][l][m]
__global__ void kT_ipct(const float* __restrict__ ipct) {
    size_t idx = (size_t)blockIdx.x * 256 + threadIdx.x;
    if (idx >= (size_t)MM * LL * HH) return;
    int h = (int)(idx % HH);
    size_t t = idx / HH;
    int l = (int)(t % LL);
    int m = (int)(t / LL);
    g_ipctT[idx] = ipct[((size_t)h * LL + l) * MM + m];
}

// ---------------- fold ------------------------------------------------------
__global__ void k_fold2(const float* __restrict__ x) {
    unsigned idx = blockIdx.x * 256u + threadIdx.x;
    if (idx >= (unsigned)(NRr * 360)) return;
    int row = idx / 360;
    int w = idx - row * 360;
    const float* xr = x + (size_t)row * WW;
    size_t b = (size_t)row * KE;
    if (w == 0) {
        split2(xr[0],   g_Eh[b + 0],   g_El[b + 0]);
        split2(xr[360], g_Eh[b + 360], g_El[b + 360]);
    } else {
        float a = xr[w], bb = xr[WW - w];
        split2(a + bb, g_Eh[b + w], g_El[b + w]);
        split2(a - bb, g_Oh[b + w - 1], g_Ol[b + w - 1]);
    }
}

// ---------------- forward MMA GEMM ------------------------------------------
// C[row][n] = sum_k (Ah+Al)[row][k] * (Bh+Bl)[n][k], 3-product split.
// Output plane-major: outBase + n*(2*NRr) + row.
#define SA_T 9216   // 128*72 elems per A tile
#define SB_T 4608   // 64*72
#define SMEM_TF 55296

__global__ __launch_bounds__(256) void tmm_f(const __nv_bfloat16* __restrict__ Ah,
                                             const __nv_bfloat16* __restrict__ Al,
                                             const __nv_bfloat16* __restrict__ Bh,
                                             const __nv_bfloat16* __restrict__ Bl,
                                             float* __restrict__ outBase) {
    extern __shared__ char smraw[];
    __nv_bfloat16* sA = (__nv_bfloat16*)smraw;      // [2][128][72]
    __nv_bfloat16* sB = sA + 2 * SA_T;              // [2][64][72]
    float* sC = (float*)smraw;                      // [128][65] (reused)
    const int tid = threadIdx.x, lid = tid & 31, wid = tid >> 5;
    const int row0 = blockIdx.x * 128, n0 = blockIdx.y * 64;
    const int wm = (wid >> 1) * 32, wn = (wid & 1) * 32;

    float d[2][4][4];
#pragma unroll
    for (int mi = 0; mi < 2; mi++)
#pragma unroll
        for (int nb = 0; nb < 4; nb++)
#pragma unroll
            for (int e = 0; e < 4; e++) d[mi][nb][e] = 0.f;

    for (int k0 = 0; k0 < KE; k0 += 64) {
#pragma unroll
        for (int p = 0; p < 4; p++) {
            int i = tid + p * 256;
            int r = i >> 3, kq = (i & 7) * 8;
            size_t g = (size_t)(row0 + r) * KE + k0 + kq;
            *(uint4*)&sA[r * 72 + kq] = *(const uint4*)&Ah[g];
            *(uint4*)&sA[SA_T + r * 72 + kq] = *(const uint4*)&Al[g];
        }
#pragma unroll
        for (int p = 0; p < 2; p++) {
            int i = tid + p * 256;
            int r = i >> 3, kq = (i & 7) * 8;
            size_t g = (size_t)(n0 + r) * KE + k0 + kq;
            *(uint4*)&sB[r * 72 + kq] = *(const uint4*)&Bh[g];
            *(uint4*)&sB[SB_T + r * 72 + kq] = *(const uint4*)&Bl[g];
        }
        __syncthreads();
#pragma unroll
        for (int ks = 0; ks < 4; ks++) {
            int kb = ks * 16;
            uint32_t ah[2][4], al[2][4], bh[2][4], bl[2][4];
#pragma unroll
            for (int mi = 0; mi < 2; mi++) {
                int off = (wm + mi * 16 + (lid & 15)) * 72 + kb + (lid >> 4) * 8;
                LDMX4(ah[mi], s2u(&sA[off]));
                LDMX4(al[mi], s2u(&sA[SA_T + off]));
            }
            int q = lid >> 3;
#pragma unroll
            for (int nh = 0; nh < 2; nh++) {
                int off = (wn + nh * 16 + (q >> 1) * 8 + (lid & 7)) * 72 + kb + (q & 1) * 8;
                LDMX4(bh[nh], s2u(&sB[off]));
                LDMX4(bl[nh], s2u(&sB[SB_T + off]));
            }
#pragma unroll
            for (int mi = 0; mi < 2; mi++)
#pragma unroll
                for (int nh = 0; nh < 2; nh++)
#pragma unroll
                    for (int nn = 0; nn < 2; nn++) {
                        float* acc = d[mi][nh * 2 + nn];
                        MMA_BF16(acc, ah[mi], bh[nh][nn * 2], bh[nh][nn * 2 + 1]);
                        MMA_BF16(acc, ah[mi], bl[nh][nn * 2], bl[nh][nn * 2 + 1]);
                        MMA_BF16(acc, al[mi], bh[nh][nn * 2], bh[nh][nn * 2 + 1]);
                    }
        }
        __syncthreads();
    }
    // epilogue: regs -> sC[row][65], then coalesced plane-major float4 stores
#pragma unroll
    for (int mi = 0; mi < 2; mi++)
#pragma unroll
        for (int nb = 0; nb < 4; nb++) {
            int r = wm + mi * 16 + (lid >> 2);
            int c = wn + nb * 8 + (lid & 3) * 2;
            sC[r * 65 + c] = d[mi][nb][0];
            sC[r * 65 + c + 1] = d[mi][nb][1];
            sC[(r + 8) * 65 + c] = d[mi][nb][2];
            sC[(r + 8) * 65 + c + 1] = d[mi][nb][3];
        }
    __syncthreads();
#pragma unroll
    for (int p = 0; p < 8; p++) {
        int i = tid + p * 256;
        int c = i >> 5, r4 = i & 31;
        float4 v = make_float4(sC[(r4 * 4 + 0) * 65 + c], sC[(r4 * 4 + 1) * 65 + c],
                               sC[(r4 * 4 + 2) * 65 + c], sC[(r4 * 4 + 3) * 65 + c]);
        *(float4*)(outBase + (size_t)(n0 + c) * (2 * NRr) + row0 + r4 * 4) = v;
    }
}

// ---------------- K2 (SIMT) -------------------------------------------------
__global__ __launch_bounds__(256) void k2_pct(const float* __restrict__ weight) {
    int m = blockIdx.z;
    int bc0 = blockIdx.x * 64;
    int l0 = blockIdx.y * 64;
    __shared__ float Ar[8][64], Ai[8][64], Ps[8][64];
    int tid = threadIdx.x;
    int tx = tid & 15;
    int ty = tid >> 4;
    float accR[4][4], accI[4][4];
#pragma unroll
    for (int i = 0; i < 4; i++)
#pragma unroll
        for (int j = 0; j < 4; j++) { accR[i][j] = 0.f; accI[i][j] = 0.f; }

    const float* xr = g_xm + (size_t)(2 * m) * NRr;
    const float* xi = xr + NRr;

    for (int h0 = 0; h0 < HH; h0 += 8) {
        {
            int r = tid >> 2;
            int k2 = (tid & 3) * 2;
            size_t base = (size_t)(bc0 + r) * HH + h0 + k2;
            float2 vr = *(const float2*)(xr + base);
            Ar[k2][r] = vr.x; Ar[k2 + 1][r] = vr.y;
            float2 vi = *(const float2*)(xi + base);
            Ai[k2][r] = vi.x; Ai[k2 + 1][r] = vi.y;
        }
        {
            int k = tid >> 5;
            int c2 = (tid & 31) * 2;
            const float* Pm = g_pctT + ((size_t)m * HH + h0 + k) * LL;
#pragma unroll
            for (int j = 0; j < 2; j++) {
                int l = l0 + c2 + j;
                Ps[k][c2 + j] = (l < LL) ? Pm[l] : 0.f;
            }
        }
        __syncthreads();
#pragma unroll
        for (int k = 0; k < 8; k++) {
            float4 ar4 = *(const float4*)&Ar[k][ty * 4];
            float4 ai4 = *(const float4*)&Ai[k][ty * 4];
            float4 p4 = *(const float4*)&Ps[k][tx * 4];
            float arv[4] = {ar4.x, ar4.y, ar4.z, ar4.w};
            float aiv[4] = {ai4.x, ai4.y, ai4.z, ai4.w};
            float pv[4] = {p4.x, p4.y, p4.z, p4.w};
#pragma unroll
            for (int i = 0; i < 4; i++)
#pragma unroll
                for (int j = 0; j < 4; j++) {
                    accR[i][j] += arv[i] * pv[j];
                    accI[i][j] += aiv[i] * pv[j];
                }
        }
        __syncthreads();
    }
    float* cr = g_cf + (size_t)(2 * m) * BCL;
    float* ci = cr + BCL;
#pragma unroll
    for (int i = 0; i < 4; i++) {
        int bc = bc0 + ty * 4 + i;
        int c = bc % CC;
#pragma unroll
        for (int j = 0; j < 4; j++) {
            int l = l0 + tx * 4 + j;
            if (l >= LL) continue;
            float2 wv = *(const float2*)(weight + (((size_t)c * LL + l) * MM + m) * 2);
            size_t o = (size_t)bc * LL + l;
            cr[o] = accR[i][j] * wv.x - accI[i][j] * wv.y;
            ci[o] = accR[i][j] * wv.y + accI[i][j] * wv.x;
        }
    }
}

// ---------------- K3 (SIMT, emits bf16 hi/lo planes) ------------------------
__global__ __launch_bounds__(256) void k3_ipct2() {
    int m = blockIdx.z;
    int bc0 = blockIdx.x * 64;
    int h0 = blockIdx.y * 64;
    __shared__ float Ar[8][64], Ai[8][64], Qs[8][64];
    int tid = threadIdx.x;
    int tx = tid & 15;
    int ty = tid >> 4;
    float accR[4][4], accI[4][4];
#pragma unroll
    for (int i = 0; i < 4; i++)
#pragma unroll
        for (int j = 0; j < 4; j++) { accR[i][j] = 0.f; accI[i][j] = 0.f; }

    const float* cr = g_cf + (size_t)(2 * m) * BCL;
    const float* ci = cr + BCL;

    for (int l0 = 0; l0 < LL; l0 += 8) {
        {
            int r = tid >> 2;
            int k2 = (tid & 3) * 2;
            int l = l0 + k2;
            size_t base = (size_t)(bc0 + r) * LL + l;
            Ar[k2][r]     = (l < LL)     ? cr[base]     : 0.f;
            Ar[k2 + 1][r] = (l + 1 < LL) ? cr[base + 1] : 0.f;
            Ai[k2][r]     = (l < LL)     ? ci[base]     : 0.f;
            Ai[k2 + 1][r] = (l + 1 < LL) ? ci[base + 1] : 0.f;
        }
        {
            int k = tid >> 5;
            int c2 = (tid & 31) * 2;
            int l = l0 + k;
            const float* Qm = g_ipctT + ((size_t)m * LL + l) * HH;
#pragma unroll
            for (int j = 0; j < 2; j++) {
                int h = h0 + c2 + j;
                Qs[k][c2 + j] = (l < LL && h < HH) ? Qm[h] : 0.f;
            }
        }
        __syncthreads();
#pragma unroll
        for (int k = 0; k < 8; k++) {
            float4 ar4 = *(const float4*)&Ar[k][ty * 4];
            float4 ai4 = *(const float4*)&Ai[k][ty * 4];
            float4 q4 = *(const float4*)&Qs[k][tx * 4];
            float arv[4] = {ar4.x, ar4.y, ar4.z, ar4.w};
            float aiv[4] = {ai4.x, ai4.y, ai4.z, ai4.w};
            float qv[4] = {q4.x, q4.y, q4.z, q4.w};
#pragma unroll
            for (int i = 0; i < 4; i++)
#pragma unroll
                for (int j = 0; j < 4; j++) {
                    accR[i][j] += arv[i] * qv[j];
                    accI[i][j] += aiv[i] * qv[j];
                }
        }
        __syncthreads();
    }
    size_t pr = (size_t)(2 * m) * NRr;
    size_t pi = pr + NRr;
#pragma unroll
    for (int i = 0; i < 4; i++) {
        int bc = bc0 + ty * 4 + i;
#pragma unroll
        for (int j = 0; j < 4; j++) {
            int h = h0 + tx * 4 + j;
            if (h >= HH) continue;
            size_t o = (size_t)bc * HH + h;
            __nv_bfloat16 hh, ll;
            split2(accR[i][j], hh, ll);
            g_x2h[pr + o] = hh; g_x2l[pr + o] = ll;
            split2(accI[i][j], hh, ll);
            g_x2h[pi + o] = hh; g_x2l[pi + o] = ll;
        }
    }
}

// ---------------- inverse MMA GEMM + fused combine --------------------------
// C[j][row] = sum_m Ic[j][m]*Re[m][row];  S[j][row] = sum_m Is[j][m]*Im[m][row].
// out[row][w=j] = C-S (j<=360); out[row][720-j] = C+S (1<=j<=359).
#define IA_T 5120   // 128*40 elems per A tile
#define IB_T 2304   // 32*72
#define SMEM_TI 66560

__global__ __launch_bounds__(256) void tmm_i(const __nv_bfloat16* __restrict__ Ich,
                                             const __nv_bfloat16* __restrict__ Icl,
                                             const __nv_bfloat16* __restrict__ Ish,
                                             const __nv_bfloat16* __restrict__ Isl,
                                             const __nv_bfloat16* __restrict__ Xh,
                                             const __nv_bfloat16* __restrict__ Xl,
                                             float* __restrict__ out) {
    extern __shared__ char smraw[];
    __nv_bfloat16* sA = (__nv_bfloat16*)smraw;      // [4][128][40] ch,cl,sh,sl
    __nv_bfloat16* sB = sA + 4 * IA_T;              // [4][32][72]  rh,rl,ih,il
    float* CsC = (float*)smraw;                     // [128][65] (reused)
    float* CsS = CsC + 128 * 65;
    const int tid = threadIdx.x, lid = tid & 31, wid = tid >> 5;
    const int row0 = blockIdx.x * 64, j0 = blockIdx.y * 128;
    const int wj = (wid >> 1) * 32, wr = (wid & 1) * 32;

    float dC[2][4][4], dS[2][4][4];
#pragma unroll
    for (int mi = 0; mi < 2; mi++)
#pragma unroll
        for (int nb = 0; nb < 4; nb++)
#pragma unroll
            for (int e = 0; e < 4; e++) { dC[mi][nb][e] = 0.f; dS[mi][nb][e] = 0.f; }

    for (int m0 = 0; m0 < NP1; m0 += 32) {
#pragma unroll
        for (int p = 0; p < 2; p++) {
            int i = tid + p * 256;
            int r = i >> 2, kq = (i & 3) * 8;
            size_t g = (size_t)(j0 + r) * NP1 + m0 + kq;
            int off = r * 40 + kq;
            *(uint4*)&sA[off] = *(const uint4*)&Ich[g];
            *(uint4*)&sA[IA_T + off] = *(const uint4*)&Icl[g];
            *(uint4*)&sA[2 * IA_T + off] = *(const uint4*)&Ish[g];
            *(uint4*)&sA[3 * IA_T + off] = *(const uint4*)&Isl[g];
        }
        {
            int mrow = tid >> 3, rq = (tid & 7) * 8;
            size_t gr = (size_t)(2 * (m0 + mrow)) * NRr + row0 + rq;
            size_t gi = gr + NRr;
            int off = mrow * 72 + rq;
            *(uint4*)&sB[off] = *(const uint4*)&Xh[gr];
            *(uint4*)&sB[IB_T + off] = *(const uint4*)&Xl[gr];
            *(uint4*)&sB[2 * IB_T + off] = *(const uint4*)&Xh[gi];
            *(uint4*)&sB[3 * IB_T + off] = *(const uint4*)&Xl[gi];
        }
        __syncthreads();
#pragma unroll
        for (int ks = 0; ks < 2; ks++) {
            int kb = ks * 16;
            int q = lid >> 3;
            {   // cos x Re -> dC
                uint32_t a0[2][4], a1[2][4], b0[2][4], b1[2][4];
#pragma unroll
                for (int mi = 0; mi < 2; mi++) {
                    int off = (wj + mi * 16 + (lid & 15)) * 40 + kb + (lid >> 4) * 8;
                    LDMX4(a0[mi], s2u(&sA[off]));
                    LDMX4(a1[mi], s2u(&sA[IA_T + off]));
                }
#pragma unroll
                for (int nh = 0; nh < 2; nh++) {
                    int off = (kb + (q & 1) * 8 + (lid & 7)) * 72 + wr + nh * 16 + (q >> 1) * 8;
                    LDMX4T(b0[nh], s2u(&sB[off]));
                    LDMX4T(b1[nh], s2u(&sB[IB_T + off]));
                }
#pragma unroll
                for (int mi = 0; mi < 2; mi++)
#pragma unroll
                    for (int nh = 0; nh < 2; nh++)
#pragma unroll
                        for (int nn = 0; nn < 2; nn++) {
                            float* acc = dC[mi][nh * 2 + nn];
                            MMA_BF16(acc, a0[mi], b0[nh][nn * 2], b0[nh][nn * 2 + 1]);
                            MMA_BF16(acc, a0[mi], b1[nh][nn * 2], b1[nh][nn * 2 + 1]);
                            MMA_BF16(acc, a1[mi], b0[nh][nn * 2], b0[nh][nn * 2 + 1]);
                        }
            }
            {   // sin x Im -> dS
                uint32_t a0[2][4], a1[2][4], b0[2][4], b1[2][4];
#pragma unroll
                for (int mi = 0; mi < 2; mi++) {
                    int off = (wj + mi * 16 + (lid & 15)) * 40 + kb + (lid >> 4) * 8;
                    LDMX4(a0[mi], s2u(&sA[2 * IA_T + off]));
                    LDMX4(a1[mi], s2u(&sA[3 * IA_T + off]));
                }
#pragma unroll
                for (int nh = 0; nh < 2; nh++) {
                    int off = (kb + (q & 1) * 8 + (lid & 7)) * 72 + wr + nh * 16 + (q >> 1) * 8;
                    LDMX4T(b0[nh], s2u(&sB[2 * IB_T + off]));
                    LDMX4T(b1[nh], s2u(&sB[3 * IB_T + off]));
                }
#pragma unroll
                for (int mi = 0; mi < 2; mi++)
#pragma unroll
                    for (int nh = 0; nh < 2; nh++)
#pragma unroll
                        for (int nn = 0; nn < 2; nn++) {
                            float* acc = dS[mi][nh * 2 + nn];
                            MMA_BF16(acc, a0[mi], b0[nh][nn * 2], b0[nh][nn * 2 + 1]);
                            MMA_BF16(acc, a0[mi], b1[nh][nn * 2], b1[nh][nn * 2 + 1]);
                            MMA_BF16(acc, a1[mi], b0[nh][nn * 2], b0[nh][nn * 2 + 1]);
                        }
            }
        }
        __syncthreads();
    }
    // epilogue: regs -> smem [j][row], then fused combine, coalesced stores
#pragma unroll
    for (int mi = 0; mi < 2; mi++)
#pragma unroll
        for (int nb = 0; nb < 4; nb++) {
            int j = wj + mi * 16 + (lid >> 2);
            int r = wr + nb * 8 + (lid & 3) * 2;
            CsC[j * 65 + r] = dC[mi][nb][0];
            CsC[j * 65 + r + 1] = dC[mi][nb][1];
            CsC[(j + 8) * 65 + r] = dC[mi][nb][2];
            CsC[(j + 8) * 65 + r + 1] = dC[mi][nb][3];
            CsS[j * 65 + r] = dS[mi][nb][0];
            CsS[j * 65 + r + 1] = dS[mi][nb][1];
            CsS[(j + 8) * 65 + r] = dS[mi][nb][2];
            CsS[(j + 8) * 65 + r + 1] = dS[mi][nb][3];
        }
    __syncthreads();
#pragma unroll
    for (int rr = 0; rr < 8; rr++) {
        int r = wid * 8 + rr;
        float* orow = out + (size_t)(row0 + r) * WW;
#pragma unroll
        for (int jt = 0; jt < 4; jt++) {
            int jj = jt * 32 + lid;
            int w = j0 + jj;
            float cv = CsC[jj * 65 + r];
            float sv = CsS[jj * 65 + r];
            if (w <= 360) orow[w] = cv - sv;
            if (w >= 1 && w <= 359) orow[WW - w] = cv + sv;
        }
    }
}

// ---------------------------------------------------------------------------
extern "C" void kernel_launch(void* const* d_in, const int* in_sizes, int n_in,
                              void* d_out, int out_size) {
    const float* x      = (const float*)d_in[0];
    const float* weight = (const float*)d_in[1];
    const float* pct    = (const float*)d_in[2];
    const float* ipct   = (const float*)d_in[3];
    float* out = (float*)d_out;

    // Resolve REAL device addresses (host-side &g_X is the shadow symbol).
    __nv_bfloat16 *p_Eh, *p_El, *p_Oh, *p_Ol;
    __nv_bfloat16 *p_Fch, *p_Fcl, *p_Fsh, *p_Fsl;
    __nv_bfloat16 *p_Ich, *p_Icl, *p_Ish, *p_Isl, *p_x2h, *p_x2l;
    float* p_xm;
    cudaGetSymbolAddress((void**)&p_Eh,  g_Eh);
    cudaGetSymbolAddress((void**)&p_El,  g_El);
    cudaGetSymbolAddress((void**)&p_Oh,  g_Oh);
    cudaGetSymbolAddress((void**)&p_Ol,  g_Ol);
    cudaGetSymbolAddress((void**)&p_Fch, g_Fch);
    cudaGetSymbolAddress((void**)&p_Fcl, g_Fcl);
    cudaGetSymbolAddress((void**)&p_Fsh, g_Fsh);
    cudaGetSymbolAddress((void**)&p_Fsl, g_Fsl);
    cudaGetSymbolAddress((void**)&p_Ich, g_Ich);
    cudaGetSymbolAddress((void**)&p_Icl, g_Icl);
    cudaGetSymbolAddress((void**)&p_Ish, g_Ish);
    cudaGetSymbolAddress((void**)&p_Isl, g_Isl);
    cudaGetSymbolAddress((void**)&p_x2h, g_x2h);
    cudaGetSymbolAddress((void**)&p_x2l, g_x2l);
    cudaGetSymbolAddress((void**)&p_xm,  g_xm);

    cudaFuncSetAttribute(tmm_f, cudaFuncAttributeMaxDynamicSharedMemorySize, SMEM_TF);
    cudaFuncSetAttribute(tmm_i, cudaFuncAttributeMaxDynamicSharedMemorySize, SMEM_TI);

    kb_f2<<<(NP1 * KE + 255) / 256, 256>>>();
    kb_i2<<<(2 * NP1 * NP1 + 255) / 256, 256>>>();
    {
        size_t n = (size_t)MM * HH * LL;
        kT_pct<<<(unsigned)((n + 255) / 256), 256>>>(pct);
        kT_ipct<<<(unsigned)((n + 255) / 256), 256>>>(ipct);
    }
    k_fold2<<<(NRr * 360 + 255) / 256, 256>>>(x);

    // Forward: Re planes = E x Fc, Im planes = O x Fs
    tmm_f<<<dim3(NRr / 128, 3), 256, SMEM_TF>>>(p_Eh, p_El, p_Fch, p_Fcl, p_xm);
    tmm_f<<<dim3(NRr / 128, 3), 256, SMEM_TF>>>(p_Oh, p_Ol, p_Fsh, p_Fsl, p_xm + NRr);

    k2_pct<<<dim3(12, 3, MM), 256>>>(weight);
    k3_ipct2<<<dim3(12, 6, MM), 256>>>();

    // Inverse + fused combine
    tmm_i<<<dim3(NRr / 64, 3), 256, SMEM_TI>>>(p_Ich, p_Icl, p_Ish, p_Isl,
                                               p_x2h, p_x2l, out);

    if ((long long)out_size >= 2LL * NTOT) {
        cudaMemcpyAsync(out + NTOT, x, (size_t)NTOT * sizeof(float),
                        cudaMemcpyDeviceToDevice);
    }
}

// round 10
// speedup vs baseline: 1.3668x; 1.3668x over previous
#include <cuda_runtime.h>
#include <math.h>
#include <stdint.h>

// Problem dims
#define BB 2
#define CC 384
#define HH 360
#define WW 720
#define LL 180
#define MM 181
#define NF 362
#define NRr 276480               // BB*CC*HH
#define BCL 138240               // BB*CC*LL
#define NTOT 199065600

#define KF 192                   // padded fold length (181 -> 192)
#define NBF 128                  // padded mode dim per parity, forward (<=96 used)
#define KI 96                    // padded K per parity, inverse (91/90 -> 96)

// ---------------- device globals (allocation-free; zero-init at load) ------
__device__ float g_fold4[4][(size_t)NRr * KF];   // EE, EO, OE, OO [row][k]
__device__ float g_Bf4[4][KF * NBF];             // fwd bases [z][k][n]
__device__ float g_Bi4[4][KI * 192];             // inv bases [z][k][j]
__device__ float g_q4[4][(size_t)NRr * KF];      // Ce, Se, Co, So [row][j]
__device__ float g_xm[(size_t)384 * NRr];        // [2m+ri][row]
__device__ float g_cf[(size_t)NF * BCL];         // [2m+ri][bc*180+l]
__device__ float g_xm2[(size_t)384 * NRr];       // [2m+ri][row]
__device__ float g_pctT[(size_t)MM * HH * LL];   // [m][h][l]
__device__ float g_ipctT[(size_t)MM * LL * HH];  // [m][l][h]

// ---------------- basis builders -------------------------------------------
// Forward z: 0 = even-m cos (A=EE), 1 = even-m -sin (A=OE),
//            2 = odd-m cos (A=EO),  3 = odd-m -sin (A=OO)
__global__ void kb_f3() {
    int idx = blockIdx.x * 256 + threadIdx.x;
    if (idx >= 4 * KF * NBF) return;
    int z = idx / (KF * NBF);
    int r = (idx / NBF) % KF;    // k index
    int n = idx % NBF;           // mode index within parity
    float v = 0.f;
    double s, c;
    if (z == 0) {                // w = r (0..180), m = 2n (n<=90)
        if (r <= 180 && n <= 90) { sincospi((double)(2 * n) * r / 360.0, &s, &c); v = (float)c; }
    } else if (z == 1) {         // w = r+1 (1..180 -> r<=179), m = 2n
        if (r <= 179 && n <= 90) { sincospi((double)(2 * n) * (r + 1) / 360.0, &s, &c); v = (float)(-s); }
    } else if (z == 2) {         // w = r, m = 2n+1 (n<=89)
        if (r <= 180 && n <= 89) { sincospi((double)(2 * n + 1) * r / 360.0, &s, &c); v = (float)c; }
    } else {                     // w = r+1, m = 2n+1
        if (r <= 179 && n <= 89) { sincospi((double)(2 * n + 1) * (r + 1) / 360.0, &s, &c); v = (float)(-s); }
    }
    g_Bf4[0][idx] = v;  // flat write across the 4 contiguous slices
}

// Inverse z: 0 = Ce (even-m cos), 1 = Se (even-m sin),
//            2 = Co (odd-m cos),  3 = So (odd-m sin). Scale c_m folded.
__global__ void kb_i3() {
    int idx = blockIdx.x * 256 + threadIdx.x;
    if (idx >= 4 * KI * 192) return;
    int z = idx / (KI * 192);
    int k = (idx / 192) % KI;
    int j = idx % 192;
    float v = 0.f;
    double s, c;
    if (j <= 180) {
        if (z < 2) {             // m = 2k, k<=90
            if (k <= 90) {
                int m = 2 * k;
                double sc = (m == 0 ? 1.0 : 2.0) / 720.0;
                sincospi((double)m * j / 360.0, &s, &c);
                v = (float)(sc * (z == 0 ? c : s));
            }
        } else {                 // m = 2k+1, k<=89
            if (k <= 89) {
                int m = 2 * k + 1;
                sincospi((double)m * j / 360.0, &s, &c);
                v = (float)((2.0 / 720.0) * (z == 2 ? c : s));
            }
        }
    }
    g_Bi4[0][idx] = v;
}

// pctT[m][h][l] = pct[h][l][m]
__global__ void kT_pct(const float* __restrict__ pct) {
    size_t idx = (size_t)blockIdx.x * 256 + threadIdx.x;
    if (idx >= (size_t)MM * HH * LL) return;
    int l = (int)(idx % LL);
    size_t t = idx / LL;
    int h = (int)(t % HH);
    int m = (int)(t / HH);
    g_pctT[idx] = pct[((size_t)h * LL + l) * MM + m];
}
// ipctT[m][l][h] = ipct[h][l][m]
__global__ void kT_ipct(const float* __restrict__ ipct) {
    size_t idx = (size_t)blockIdx.x * 256 + threadIdx.x;
    if (idx >= (size_t)MM * LL * HH) return;
    int h = (int)(idx % HH);
    size_t t = idx / HH;
    int l = (int)(t % LL);
    int m = (int)(t / LL);
    g_ipctT[idx] = ipct[((size_t)h * LL + l) * MM + m];
}

// ---------------- double fold ----------------------------------------------
// E[w]=x[w]+x[720-w], O[w]=x[w]-x[720-w]; then fold about 360:
// EE[w]=E[w]+E[360-w], EO[w]=E[w]-E[360-w] (w=0..179, self@180),
// OE[w-1]=O[w]-O[360-w], OO[w-1]=O[w]+O[360-w] (w=1..179, self@180).
__global__ void k_fold4(const float* __restrict__ x, float* __restrict__ fold) {
    unsigned idx = blockIdx.x * 256u + threadIdx.x;
    if (idx >= (unsigned)NRr * 181u) return;
    int row = idx / 181;
    int w = idx - row * 181;
    const float* xr = x + (size_t)row * WW;
    float* EE = fold + (size_t)row * KF;
    float* EO = EE + (size_t)NRr * KF;
    float* OE = EO + (size_t)NRr * KF;
    float* OO = OE + (size_t)NRr * KF;
    if (w == 0) {
        EE[0] = xr[0] + xr[360];
        EO[0] = xr[0] - xr[360];
    } else if (w == 180) {
        float a = xr[180], b = xr[540];
        EE[180] = a + b;
        EO[180] = 0.f;
        OE[179] = 0.f;
        OO[179] = a - b;
    } else {
        float x1 = xr[w], x2 = xr[WW - w], x3 = xr[360 - w], x4 = xr[360 + w];
        EE[w] = x1 + x2 + x3 + x4;
        EO[w] = x1 + x2 - x3 - x4;
        OE[w - 1] = x1 - x2 - x3 + x4;
        OO[w - 1] = x1 - x2 + x3 - x4;
    }
}

// ---------------- forward GEMM (4 parity GEMMs via blockIdx.z) --------------
// xm[4n+z][row] = sum_k fold[Aidx(z)][row][k] * Bf[z][k][n]
__global__ __launch_bounds__(256) void g1f(const float* __restrict__ fold,
                                           const float* __restrict__ Bf,
                                           float* __restrict__ xm) {
    __shared__ float As[16][132];
    __shared__ float Bs[16][68];
    int z = blockIdx.z;
    int Aidx = ((z & 1) << 1) | ((z >> 1) & 1);   // 0->EE,1->OE,2->EO,3->OO
    const float* A = fold + (size_t)Aidx * NRr * KF;
    const float* Bb = Bf + (size_t)z * (KF * NBF);
    int row0 = blockIdx.x * 128;
    int n0 = blockIdx.y * 64;
    int tid = threadIdx.x;
    int tx = tid & 31;   // row micro (x4)
    int ty = tid >> 5;   // n micro (x8)
    float acc[8][4];
#pragma unroll
    for (int j = 0; j < 8; j++)
#pragma unroll
        for (int i = 0; i < 4; i++) acc[j][i] = 0.f;

    int lr = tid >> 1, lkq = (tid & 1) * 8;
    int lkb = tid >> 4, lnv = (tid & 15) * 4;
    const float* arow = A + (size_t)(row0 + lr) * KF + lkq;

    for (int k0 = 0; k0 < KF; k0 += 16) {
        {
            float4 v0 = *(const float4*)(arow + k0);
            float4 v1 = *(const float4*)(arow + k0 + 4);
            As[lkq + 0][lr] = v0.x; As[lkq + 1][lr] = v0.y;
            As[lkq + 2][lr] = v0.z; As[lkq + 3][lr] = v0.w;
            As[lkq + 4][lr] = v1.x; As[lkq + 5][lr] = v1.y;
            As[lkq + 6][lr] = v1.z; As[lkq + 7][lr] = v1.w;
        }
        *(float4*)&Bs[lkb][lnv] =
            *(const float4*)(Bb + (size_t)(k0 + lkb) * NBF + n0 + lnv);
        __syncthreads();
#pragma unroll
        for (int kk = 0; kk < 16; kk++) {
            float4 a4 = *(const float4*)&As[kk][tx * 4];
            float4 b0 = *(const float4*)&Bs[kk][ty * 8];
            float4 b1 = *(const float4*)&Bs[kk][ty * 8 + 4];
            float av[4] = {a4.x, a4.y, a4.z, a4.w};
            float bv[8] = {b0.x, b0.y, b0.z, b0.w, b1.x, b1.y, b1.z, b1.w};
#pragma unroll
            for (int j = 0; j < 8; j++)
#pragma unroll
                for (int i = 0; i < 4; i++) acc[j][i] += bv[j] * av[i];
        }
        __syncthreads();
    }
#pragma unroll
    for (int j = 0; j < 8; j++) {
        int n = n0 + ty * 8 + j;
        if (n >= 96) continue;
        size_t p = (size_t)(4 * n + z);
        float4 st = make_float4(acc[j][0], acc[j][1], acc[j][2], acc[j][3]);
        *(float4*)(xm + p * NRr + row0 + tx * 4) = st;
    }
}

// ---------------- K2 (SIMT, verbatim R7) ------------------------------------
__global__ __launch_bounds__(256) void k2_pct(const float* __restrict__ weight) {
    int m = blockIdx.z;
    int bc0 = blockIdx.x * 64;
    int l0 = blockIdx.y * 64;
    __shared__ float Ar[8][64], Ai[8][64], Ps[8][64];
    int tid = threadIdx.x;
    int tx = tid & 15;
    int ty = tid >> 4;
    float accR[4][4], accI[4][4];
#pragma unroll
    for (int i = 0; i < 4; i++)
#pragma unroll
        for (int j = 0; j < 4; j++) { accR[i][j] = 0.f; accI[i][j] = 0.f; }

    const float* xr = g_xm + (size_t)(2 * m) * NRr;
    const float* xi = xr + NRr;

    for (int h0 = 0; h0 < HH; h0 += 8) {
        {
            int r = tid >> 2;
            int k2 = (tid & 3) * 2;
            size_t base = (size_t)(bc0 + r) * HH + h0 + k2;
            float2 vr = *(const float2*)(xr + base);
            Ar[k2][r] = vr.x; Ar[k2 + 1][r] = vr.y;
            float2 vi = *(const float2*)(xi + base);
            Ai[k2][r] = vi.x; Ai[k2 + 1][r] = vi.y;
        }
        {
            int k = tid >> 5;
            int c2 = (tid & 31) * 2;
            const float* Pm = g_pctT + ((size_t)m * HH + h0 + k) * LL;
#pragma unroll
            for (int j = 0; j < 2; j++) {
                int l = l0 + c2 + j;
                Ps[k][c2 + j] = (l < LL) ? Pm[l] : 0.f;
            }
        }
        __syncthreads();
#pragma unroll
        for (int k = 0; k < 8; k++) {
            float4 ar4 = *(const float4*)&Ar[k][ty * 4];
            float4 ai4 = *(const float4*)&Ai[k][ty * 4];
            float4 p4 = *(const float4*)&Ps[k][tx * 4];
            float arv[4] = {ar4.x, ar4.y, ar4.z, ar4.w};
            float aiv[4] = {ai4.x, ai4.y, ai4.z, ai4.w};
            float pv[4] = {p4.x, p4.y, p4.z, p4.w};
#pragma unroll
            for (int i = 0; i < 4; i++)
#pragma unroll
                for (int j = 0; j < 4; j++) {
                    accR[i][j] += arv[i] * pv[j];
                    accI[i][j] += aiv[i] * pv[j];
                }
        }
        __syncthreads();
    }
    float* cr = g_cf + (size_t)(2 * m) * BCL;
    float* ci = cr + BCL;
#pragma unroll
    for (int i = 0; i < 4; i++) {
        int bc = bc0 + ty * 4 + i;
        int c = bc % CC;
#pragma unroll
        for (int j = 0; j < 4; j++) {
            int l = l0 + tx * 4 + j;
            if (l >= LL) continue;
            float2 wv = *(const float2*)(weight + (((size_t)c * LL + l) * MM + m) * 2);
            size_t o = (size_t)bc * LL + l;
            cr[o] = accR[i][j] * wv.x - accI[i][j] * wv.y;
            ci[o] = accR[i][j] * wv.y + accI[i][j] * wv.x;
        }
    }
}

// ---------------- K3 (SIMT, verbatim R7, fp32 out) --------------------------
__global__ __launch_bounds__(256) void k3_ipct() {
    int m = blockIdx.z;
    int bc0 = blockIdx.x * 64;
    int h0 = blockIdx.y * 64;
    __shared__ float Ar[8][64], Ai[8][64], Qs[8][64];
    int tid = threadIdx.x;
    int tx = tid & 15;
    int ty = tid >> 4;
    float accR[4][4], accI[4][4];
#pragma unroll
    for (int i = 0; i < 4; i++)
#pragma unroll
        for (int j = 0; j < 4; j++) { accR[i][j] = 0.f; accI[i][j] = 0.f; }

    const float* cr = g_cf + (size_t)(2 * m) * BCL;
    const float* ci = cr + BCL;

    for (int l0 = 0; l0 < LL; l0 += 8) {
        {
            int r = tid >> 2;
            int k2 = (tid & 3) * 2;
            int l = l0 + k2;
            size_t base = (size_t)(bc0 + r) * LL + l;
            Ar[k2][r]     = (l < LL)     ? cr[base]     : 0.f;
            Ar[k2 + 1][r] = (l + 1 < LL) ? cr[base + 1] : 0.f;
            Ai[k2][r]     = (l < LL)     ? ci[base]     : 0.f;
            Ai[k2 + 1][r] = (l + 1 < LL) ? ci[base + 1] : 0.f;
        }
        {
            int k = tid >> 5;
            int c2 = (tid & 31) * 2;
            int l = l0 + k;
            const float* Qm = g_ipctT + ((size_t)m * LL + l) * HH;
#pragma unroll
            for (int j = 0; j < 2; j++) {
                int h = h0 + c2 + j;
                Qs[k][c2 + j] = (l < LL && h < HH) ? Qm[h] : 0.f;
            }
        }
        __syncthreads();
#pragma unroll
        for (int k = 0; k < 8; k++) {
            float4 ar4 = *(const float4*)&Ar[k][ty * 4];
            float4 ai4 = *(const float4*)&Ai[k][ty * 4];
            float4 q4 = *(const float4*)&Qs[k][tx * 4];
            float arv[4] = {ar4.x, ar4.y, ar4.z, ar4.w};
            float aiv[4] = {ai4.x, ai4.y, ai4.z, ai4.w};
            float qv[4] = {q4.x, q4.y, q4.z, q4.w};
#pragma unroll
            for (int i = 0; i < 4; i++)
#pragma unroll
                for (int j = 0; j < 4; j++) {
                    accR[i][j] += arv[i] * qv[j];
                    accI[i][j] += aiv[i] * qv[j];
                }
        }
        __syncthreads();
    }
    float* orp = g_xm2 + (size_t)(2 * m) * NRr;
    float* oip = orp + NRr;
#pragma unroll
    for (int i = 0; i < 4; i++) {
        int bc = bc0 + ty * 4 + i;
#pragma unroll
        for (int j = 0; j < 4; j++) {
            int h = h0 + tx * 4 + j;
            if (h >= HH) continue;
            size_t o = (size_t)bc * HH + h;
            orp[o] = accR[i][j];
            oip[o] = accI[i][j];
        }
    }
}

// ---------------- inverse GEMM (4 parity GEMMs via blockIdx.z) --------------
// q[z][row][j] = sum_k xm2[4k+z][row] * Bi[z][k][j], j=0..191, K=96
__global__ __launch_bounds__(256) void g4b(const float* __restrict__ xm2,
                                           const float* __restrict__ Bi,
                                           float* __restrict__ q) {
    __shared__ float As[16][132];
    __shared__ float Bs[16][68];
    int z = blockIdx.z;
    const float* Bb = Bi + (size_t)z * (KI * 192);
    float* qz = q + (size_t)z * NRr * KF;
    int row0 = blockIdx.x * 128;
    int j0 = blockIdx.y * 64;
    int tid = threadIdx.x;
    int tx = tid & 15;   // j micro (x4)
    int ty = tid >> 4;   // row micro (x8)
    float acc[8][4];
#pragma unroll
    for (int i = 0; i < 8; i++)
#pragma unroll
        for (int j = 0; j < 4; j++) acc[i][j] = 0.f;

    int lkb = tid >> 4, lrv = (tid & 15) * 8;
    int lnv = (tid & 15) * 4;

    for (int k0 = 0; k0 < KI; k0 += 16) {
        {
            const float* src = xm2 + (size_t)(4 * (k0 + lkb) + z) * NRr + row0 + lrv;
            float4 v0 = *(const float4*)src;
            float4 v1 = *(const float4*)(src + 4);
            *(float4*)&As[lkb][lrv] = v0;
            *(float4*)&As[lkb][lrv + 4] = v1;
        }
        *(float4*)&Bs[lkb][lnv] =
            *(const float4*)(Bb + (size_t)(k0 + lkb) * 192 + j0 + lnv);
        __syncthreads();
#pragma unroll
        for (int kk = 0; kk < 16; kk++) {
            float4 b4 = *(const float4*)&Bs[kk][tx * 4];
            float4 a0 = *(const float4*)&As[kk][ty * 8];
            float4 a1 = *(const float4*)&As[kk][ty * 8 + 4];
            float bv[4] = {b4.x, b4.y, b4.z, b4.w};
            float av[8] = {a0.x, a0.y, a0.z, a0.w, a1.x, a1.y, a1.z, a1.w};
#pragma unroll
            for (int i = 0; i < 8; i++)
#pragma unroll
                for (int j = 0; j < 4; j++) acc[i][j] += av[i] * bv[j];
        }
        __syncthreads();
    }
#pragma unroll
    for (int i = 0; i < 8; i++) {
        int row = row0 + ty * 8 + i;
        float4 st = make_float4(acc[i][0], acc[i][1], acc[i][2], acc[i][3]);
        *(float4*)(qz + (size_t)row * KF + j0 + tx * 4) = st;
    }
}

// ---------------- combine (4-quadrant reconstruction) -----------------------
__global__ void k_comb4(const float* __restrict__ q, float* __restrict__ out) {
    unsigned idx = blockIdx.x * 256u + threadIdx.x;
    if (idx >= (unsigned)NRr * 181u) return;
    int row = idx / 181;
    int j = idx - row * 181;
    const float* qr = q + (size_t)row * KF + j;
    const size_t zs = (size_t)NRr * KF;
    float q0 = qr[0], q1 = qr[zs], q2 = qr[2 * zs], q3 = qr[3 * zs];
    float a = q0 + q2, b = q1 + q3, c = q0 - q2, d = q1 - q3;
    float* o = out + (size_t)row * WW;
    o[j] = a - b;
    o[360 - j] = c + d;
    if (j >= 1) {
        o[WW - j] = a + b;
        o[360 + j] = c - d;
    }
}

// ---------------------------------------------------------------------------
extern "C" void kernel_launch(void* const* d_in, const int* in_sizes, int n_in,
                              void* d_out, int out_size) {
    const float* x      = (const float*)d_in[0];
    const float* weight = (const float*)d_in[1];
    const float* pct    = (const float*)d_in[2];
    const float* ipct   = (const float*)d_in[3];
    float* out = (float*)d_out;

    // Resolve REAL device addresses (host-side &symbol is the shadow).
    float *p_fold, *p_Bf, *p_Bi, *p_q, *p_xm, *p_xm2;
    cudaGetSymbolAddress((void**)&p_fold, g_fold4);
    cudaGetSymbolAddress((void**)&p_Bf,   g_Bf4);
    cudaGetSymbolAddress((void**)&p_Bi,   g_Bi4);
    cudaGetSymbolAddress((void**)&p_q,    g_q4);
    cudaGetSymbolAddress((void**)&p_xm,   g_xm);
    cudaGetSymbolAddress((void**)&p_xm2,  g_xm2);

    kb_f3<<<(4 * KF * NBF + 255) / 256, 256>>>();
    kb_i3<<<(4 * KI * 192 + 255) / 256, 256>>>();
    {
        size_t n = (size_t)MM * HH * LL;
        kT_pct<<<(unsigned)((n + 255) / 256), 256>>>(pct);
        kT_ipct<<<(unsigned)((n + 255) / 256), 256>>>(ipct);
    }
    k_fold4<<<(NRr * 181 + 255) / 256, 256>>>(x, p_fold);

    // Forward: 4 parity GEMMs in one launch (z = parity/trig class)
    g1f<<<dim3(NRr / 128, 2, 4), 256>>>(p_fold, p_Bf, p_xm);

    k2_pct<<<dim3(12, 3, MM), 256>>>(weight);
    k3_ipct<<<dim3(12, 6, MM), 256>>>();

    // Inverse: 4 parity syntheses in one launch
    g4b<<<dim3(NRr / 128, 3, 4), 256>>>(p_xm2, p_Bi, p_q);

    k_comb4<<<(NRr * 181 + 255) / 256, 256>>>(p_q, out);

    if ((long long)out_size >= 2LL * NTOT) {
        cudaMemcpyAsync(out + NTOT, x, (size_t)NTOT * sizeof(float),
                        cudaMemcpyDeviceToDevice);
    }
}

// round 11
// speedup vs baseline: 1.3847x; 1.0131x over previous
#include <cuda_runtime.h>
#include <math.h>
#include <stdint.h>

// Problem dims
#define BB 2
#define CC 384
#define HH 360
#define WW 720
#define LL 180
#define MM 181
#define NF 362
#define NRr 276480               // BB*CC*HH
#define BCL 138240               // BB*CC*LL
#define NTOT 199065600

#define KF 192                   // padded fold length (181 -> 192)
#define NBF 96                   // padded mode dim per parity (91/90 -> 96)
#define KI 96                    // padded K per parity, inverse

// ---------------- device globals (allocation-free; zero-init at load) ------
__device__ float g_fold4[4][(size_t)NRr * KF];   // EE, EO, OE, OO [row][k]
__device__ float g_Bf4[4][KF * NBF];             // fwd bases [z][k][n]
__device__ float g_Bi4[4][KI * 192];             // inv bases [z][k][j]
__device__ float g_xm[(size_t)384 * NRr];        // [plane][row], plane=4n+z
__device__ float g_cf[(size_t)NF * BCL];         // [2m+ri][bc*180+l]
__device__ float g_xm2[(size_t)384 * NRr];       // [plane][row]
__device__ float g_pctT[(size_t)MM * HH * LL];   // [m][h][l]
__device__ float g_ipctT[(size_t)MM * LL * HH];  // [m][l][h]

// ---------------- basis builders -------------------------------------------
// Forward z: 0 = even-m cos (A=EE), 1 = even-m -sin (A=OE),
//            2 = odd-m cos (A=EO),  3 = odd-m -sin (A=OO)
__global__ void kb_f3() {
    int idx = blockIdx.x * 256 + threadIdx.x;
    if (idx >= 4 * KF * NBF) return;
    int z = idx / (KF * NBF);
    int r = (idx / NBF) % KF;    // k index
    int n = idx % NBF;           // mode index within parity
    float v = 0.f;
    double s, c;
    if (z == 0) {                // w = r (0..180), m = 2n (n<=90)
        if (r <= 180 && n <= 90) { sincospi((double)(2 * n) * r / 360.0, &s, &c); v = (float)c; }
    } else if (z == 1) {         // w = r+1 (1..180), m = 2n
        if (r <= 179 && n <= 90) { sincospi((double)(2 * n) * (r + 1) / 360.0, &s, &c); v = (float)(-s); }
    } else if (z == 2) {         // w = r, m = 2n+1 (n<=89)
        if (r <= 180 && n <= 89) { sincospi((double)(2 * n + 1) * r / 360.0, &s, &c); v = (float)c; }
    } else {                     // w = r+1, m = 2n+1
        if (r <= 179 && n <= 89) { sincospi((double)(2 * n + 1) * (r + 1) / 360.0, &s, &c); v = (float)(-s); }
    }
    g_Bf4[0][idx] = v;
}

// Inverse z: 0 = Ce (even-m cos), 1 = Se (even-m sin),
//            2 = Co (odd-m cos),  3 = So (odd-m sin). Scale c_m folded.
__global__ void kb_i3() {
    int idx = blockIdx.x * 256 + threadIdx.x;
    if (idx >= 4 * KI * 192) return;
    int z = idx / (KI * 192);
    int k = (idx / 192) % KI;
    int j = idx % 192;
    float v = 0.f;
    double s, c;
    if (j <= 180) {
        if (z < 2) {
            if (k <= 90) {
                int m = 2 * k;
                double sc = (m == 0 ? 1.0 : 2.0) / 720.0;
                sincospi((double)m * j / 360.0, &s, &c);
                v = (float)(sc * (z == 0 ? c : s));
            }
        } else {
            if (k <= 89) {
                int m = 2 * k + 1;
                sincospi((double)m * j / 360.0, &s, &c);
                v = (float)((2.0 / 720.0) * (z == 2 ? c : s));
            }
        }
    }
    g_Bi4[0][idx] = v;
}

// pctT[m][h][l] = pct[h][l][m]
__global__ void kT_pct(const float* __restrict__ pct) {
    size_t idx = (size_t)blockIdx.x * 256 + threadIdx.x;
    if (idx >= (size_t)MM * HH * LL) return;
    int l = (int)(idx % LL);
    size_t t = idx / LL;
    int h = (int)(t % HH);
    int m = (int)(t / HH);
    g_pctT[idx] = pct[((size_t)h * LL + l) * MM + m];
}
// ipctT[m][l][h] = ipct[h][l][m]
__global__ void kT_ipct(const float* __restrict__ ipct) {
    size_t idx = (size_t)blockIdx.x * 256 + threadIdx.x;
    if (idx >= (size_t)MM * LL * HH) return;
    int h = (int)(idx % HH);
    size_t t = idx / HH;
    int l = (int)(t % LL);
    int m = (int)(t / LL);
    g_ipctT[idx] = ipct[((size_t)h * LL + l) * MM + m];
}

// ---------------- double fold ----------------------------------------------
__global__ void k_fold4(const float* __restrict__ x, float* __restrict__ fold) {
    unsigned idx = blockIdx.x * 256u + threadIdx.x;
    if (idx >= (unsigned)NRr * 181u) return;
    int row = idx / 181;
    int w = idx - row * 181;
    const float* xr = x + (size_t)row * WW;
    float* EE = fold + (size_t)row * KF;
    float* EO = EE + (size_t)NRr * KF;
    float* OE = EO + (size_t)NRr * KF;
    float* OO = OE + (size_t)NRr * KF;
    if (w == 0) {
        EE[0] = xr[0] + xr[360];
        EO[0] = xr[0] - xr[360];
    } else if (w == 180) {
        float a = xr[180], b = xr[540];
        EE[180] = a + b;
        EO[180] = 0.f;
        OE[179] = 0.f;
        OO[179] = a - b;
    } else {
        float x1 = xr[w], x2 = xr[WW - w], x3 = xr[360 - w], x4 = xr[360 + w];
        EE[w] = x1 + x2 + x3 + x4;
        EO[w] = x1 + x2 - x3 - x4;
        OE[w - 1] = x1 - x2 - x3 + x4;
        OO[w - 1] = x1 - x2 + x3 - x4;
    }
}

// ---------------- forward GEMM: 128 rows x 96 modes, no pad waste ----------
// xm[4n+z][row] = sum_k fold[Aidx(z)][row][k] * Bf[z][k][n]
__global__ __launch_bounds__(256) void g1f96(const float* __restrict__ fold,
                                             const float* __restrict__ Bf,
                                             float* __restrict__ xm) {
    __shared__ float As[16][132];
    __shared__ float Bs[16][96];
    int z = blockIdx.y;
    int Aidx = ((z & 1) << 1) | ((z >> 1) & 1);   // 0->EE,1->OE,2->EO,3->OO
    const float* A = fold + (size_t)Aidx * NRr * KF;
    const float* Bb = Bf + (size_t)z * (KF * NBF);
    int row0 = blockIdx.x * 128;
    int tid = threadIdx.x;
    int tx = tid & 31;   // row micro (x4)
    int ty = tid >> 5;   // col micro (x12)
    float acc[12][4];
#pragma unroll
    for (int j = 0; j < 12; j++)
#pragma unroll
        for (int i = 0; i < 4; i++) acc[j][i] = 0.f;

    int lr = tid >> 1, lkq = (tid & 1) * 8;
    const float* arow = A + (size_t)(row0 + lr) * KF + lkq;

    for (int k0 = 0; k0 < KF; k0 += 16) {
        {
            float4 v0 = *(const float4*)(arow + k0);
            float4 v1 = *(const float4*)(arow + k0 + 4);
            As[lkq + 0][lr] = v0.x; As[lkq + 1][lr] = v0.y;
            As[lkq + 2][lr] = v0.z; As[lkq + 3][lr] = v0.w;
            As[lkq + 4][lr] = v1.x; As[lkq + 5][lr] = v1.y;
            As[lkq + 6][lr] = v1.z; As[lkq + 7][lr] = v1.w;
        }
#pragma unroll
        for (int p = 0; p < 2; p++) {
            int i = tid + p * 256;
            if (i < 384) {
                int k = i / 24, c4 = (i % 24) * 4;
                *(float4*)&Bs[k][c4] = *(const float4*)(Bb + (size_t)(k0 + k) * NBF + c4);
            }
        }
        __syncthreads();
#pragma unroll
        for (int kk = 0; kk < 16; kk++) {
            float4 a4 = *(const float4*)&As[kk][tx * 4];
            float4 b0 = *(const float4*)&Bs[kk][ty * 12];
            float4 b1 = *(const float4*)&Bs[kk][ty * 12 + 4];
            float4 b2 = *(const float4*)&Bs[kk][ty * 12 + 8];
            float av[4] = {a4.x, a4.y, a4.z, a4.w};
            float bv[12] = {b0.x, b0.y, b0.z, b0.w, b1.x, b1.y, b1.z, b1.w,
                            b2.x, b2.y, b2.z, b2.w};
#pragma unroll
            for (int j = 0; j < 12; j++)
#pragma unroll
                for (int i = 0; i < 4; i++) acc[j][i] += bv[j] * av[i];
        }
        __syncthreads();
    }
#pragma unroll
    for (int j = 0; j < 12; j++) {
        int n = ty * 12 + j;   // 0..95, planes 4n+z all exist (384 planes)
        size_t p = (size_t)(4 * n + z);
        float4 st = make_float4(acc[j][0], acc[j][1], acc[j][2], acc[j][3]);
        *(float4*)(xm + p * NRr + row0 + tx * 4) = st;
    }
}

// ---------------- K2 (SIMT, verbatim R10) -----------------------------------
__global__ __launch_bounds__(256) void k2_pct(const float* __restrict__ weight) {
    int m = blockIdx.z;
    int bc0 = blockIdx.x * 64;
    int l0 = blockIdx.y * 64;
    __shared__ float Ar[8][64], Ai[8][64], Ps[8][64];
    int tid = threadIdx.x;
    int tx = tid & 15;
    int ty = tid >> 4;
    float accR[4][4], accI[4][4];
#pragma unroll
    for (int i = 0; i < 4; i++)
#pragma unroll
        for (int j = 0; j < 4; j++) { accR[i][j] = 0.f; accI[i][j] = 0.f; }

    const float* xr = g_xm + (size_t)(2 * m) * NRr;
    const float* xi = xr + NRr;

    for (int h0 = 0; h0 < HH; h0 += 8) {
        {
            int r = tid >> 2;
            int k2 = (tid & 3) * 2;
            size_t base = (size_t)(bc0 + r) * HH + h0 + k2;
            float2 vr = *(const float2*)(xr + base);
            Ar[k2][r] = vr.x; Ar[k2 + 1][r] = vr.y;
            float2 vi = *(const float2*)(xi + base);
            Ai[k2][r] = vi.x; Ai[k2 + 1][r] = vi.y;
        }
        {
            int k = tid >> 5;
            int c2 = (tid & 31) * 2;
            const float* Pm = g_pctT + ((size_t)m * HH + h0 + k) * LL;
#pragma unroll
            for (int j = 0; j < 2; j++) {
                int l = l0 + c2 + j;
                Ps[k][c2 + j] = (l < LL) ? Pm[l] : 0.f;
            }
        }
        __syncthreads();
#pragma unroll
        for (int k = 0; k < 8; k++) {
            float4 ar4 = *(const float4*)&Ar[k][ty * 4];
            float4 ai4 = *(const float4*)&Ai[k][ty * 4];
            float4 p4 = *(const float4*)&Ps[k][tx * 4];
            float arv[4] = {ar4.x, ar4.y, ar4.z, ar4.w};
            float aiv[4] = {ai4.x, ai4.y, ai4.z, ai4.w};
            float pv[4] = {p4.x, p4.y, p4.z, p4.w};
#pragma unroll
            for (int i = 0; i < 4; i++)
#pragma unroll
                for (int j = 0; j < 4; j++) {
                    accR[i][j] += arv[i] * pv[j];
                    accI[i][j] += aiv[i] * pv[j];
                }
        }
        __syncthreads();
    }
    float* cr = g_cf + (size_t)(2 * m) * BCL;
    float* ci = cr + BCL;
#pragma unroll
    for (int i = 0; i < 4; i++) {
        int bc = bc0 + ty * 4 + i;
        int c = bc % CC;
#pragma unroll
        for (int j = 0; j < 4; j++) {
            int l = l0 + tx * 4 + j;
            if (l >= LL) continue;
            float2 wv = *(const float2*)(weight + (((size_t)c * LL + l) * MM + m) * 2);
            size_t o = (size_t)bc * LL + l;
            cr[o] = accR[i][j] * wv.x - accI[i][j] * wv.y;
            ci[o] = accR[i][j] * wv.y + accI[i][j] * wv.x;
        }
    }
}

// ---------------- K3 (SIMT, verbatim R10) -----------------------------------
__global__ __launch_bounds__(256) void k3_ipct() {
    int m = blockIdx.z;
    int bc0 = blockIdx.x * 64;
    int h0 = blockIdx.y * 64;
    __shared__ float Ar[8][64], Ai[8][64], Qs[8][64];
    int tid = threadIdx.x;
    int tx = tid & 15;
    int ty = tid >> 4;
    float accR[4][4], accI[4][4];
#pragma unroll
    for (int i = 0; i < 4; i++)
#pragma unroll
        for (int j = 0; j < 4; j++) { accR[i][j] = 0.f; accI[i][j] = 0.f; }

    const float* cr = g_cf + (size_t)(2 * m) * BCL;
    const float* ci = cr + BCL;

    for (int l0 = 0; l0 < LL; l0 += 8) {
        {
            int r = tid >> 2;
            int k2 = (tid & 3) * 2;
            int l = l0 + k2;
            size_t base = (size_t)(bc0 + r) * LL + l;
            Ar[k2][r]     = (l < LL)     ? cr[base]     : 0.f;
            Ar[k2 + 1][r] = (l + 1 < LL) ? cr[base + 1] : 0.f;
            Ai[k2][r]     = (l < LL)     ? ci[base]     : 0.f;
            Ai[k2 + 1][r] = (l + 1 < LL) ? ci[base + 1] : 0.f;
        }
        {
            int k = tid >> 5;
            int c2 = (tid & 31) * 2;
            int l = l0 + k;
            const float* Qm = g_ipctT + ((size_t)m * LL + l) * HH;
#pragma unroll
            for (int j = 0; j < 2; j++) {
                int h = h0 + c2 + j;
                Qs[k][c2 + j] = (l < LL && h < HH) ? Qm[h] : 0.f;
            }
        }
        __syncthreads();
#pragma unroll
        for (int k = 0; k < 8; k++) {
            float4 ar4 = *(const float4*)&Ar[k][ty * 4];
            float4 ai4 = *(const float4*)&Ai[k][ty * 4];
            float4 q4 = *(const float4*)&Qs[k][tx * 4];
            float arv[4] = {ar4.x, ar4.y, ar4.z, ar4.w};
            float aiv[4] = {ai4.x, ai4.y, ai4.z, ai4.w};
            float qv[4] = {q4.x, q4.y, q4.z, q4.w};
#pragma unroll
            for (int i = 0; i < 4; i++)
#pragma unroll
                for (int j = 0; j < 4; j++) {
                    accR[i][j] += arv[i] * qv[j];
                    accI[i][j] += aiv[i] * qv[j];
                }
        }
        __syncthreads();
    }
    float* orp = g_xm2 + (size_t)(2 * m) * NRr;
    float* oip = orp + NRr;
#pragma unroll
    for (int i = 0; i < 4; i++) {
        int bc = bc0 + ty * 4 + i;
#pragma unroll
        for (int j = 0; j < 4; j++) {
            int h = h0 + tx * 4 + j;
            if (h >= HH) continue;
            size_t o = (size_t)bc * HH + h;
            orp[o] = accR[i][j];
            oip[o] = accI[i][j];
        }
    }
}

// ---------------- inverse GEMM + fused 4-quadrant combine -------------------
// Per block: 64 rows x 64 j, all 4 parity classes (K=96 each), then
// out[j]=a-b, out[360-j]=c+d, out[720-j]=a+b, out[360+j]=c-d.
__global__ __launch_bounds__(256) void g4c(const float* __restrict__ xm2,
                                           const float* __restrict__ Bi,
                                           float* __restrict__ out) {
    __shared__ float As[4][16][68];
    __shared__ float Bs[4][16][68];
    int row0 = blockIdx.x * 64;
    int j0 = blockIdx.y * 64;
    int tid = threadIdx.x;
    int tx = tid & 15;   // j micro (x4)
    int ty = tid >> 4;   // row micro (x4)
    float acc[4][4][4];  // [z][row i][j]
#pragma unroll
    for (int z = 0; z < 4; z++)
#pragma unroll
        for (int i = 0; i < 4; i++)
#pragma unroll
            for (int j = 0; j < 4; j++) acc[z][i][j] = 0.f;

    for (int k0 = 0; k0 < KI; k0 += 16) {
#pragma unroll
        for (int p = 0; p < 4; p++) {
            int i = tid + p * 256;
            int z = i >> 8, k = (i >> 4) & 15, c4 = (i & 15) * 4;
            *(float4*)&As[z][k][c4] =
                *(const float4*)(xm2 + (size_t)(4 * (k0 + k) + z) * NRr + row0 + c4);
            *(float4*)&Bs[z][k][c4] =
                *(const float4*)(Bi + (size_t)z * (KI * 192) + (size_t)(k0 + k) * 192 + j0 + c4);
        }
        __syncthreads();
#pragma unroll
        for (int kk = 0; kk < 16; kk++) {
#pragma unroll
            for (int z = 0; z < 4; z++) {
                float4 a4 = *(const float4*)&As[z][kk][ty * 4];
                float4 b4 = *(const float4*)&Bs[z][kk][tx * 4];
                float av[4] = {a4.x, a4.y, a4.z, a4.w};
                float bv[4] = {b4.x, b4.y, b4.z, b4.w};
#pragma unroll
                for (int i = 0; i < 4; i++)
#pragma unroll
                    for (int j = 0; j < 4; j++) acc[z][i][j] += av[i] * bv[j];
            }
        }
        __syncthreads();
    }
    // fused combine epilogue
#pragma unroll
    for (int i = 0; i < 4; i++) {
        int row = row0 + ty * 4 + i;
        float* o = out + (size_t)row * WW;
#pragma unroll
        for (int j = 0; j < 4; j++) {
            int jj = j0 + tx * 4 + j;
            if (jj > 180) continue;
            float q0 = acc[0][i][j], q1 = acc[1][i][j];
            float q2 = acc[2][i][j], q3 = acc[3][i][j];
            float a = q0 + q2, b = q1 + q3, c = q0 - q2, d = q1 - q3;
            o[jj] = a - b;
            o[360 - jj] = c + d;
            if (jj >= 1) {
                o[WW - jj] = a + b;
                o[360 + jj] = c - d;
            }
        }
    }
}

// ---------------------------------------------------------------------------
extern "C" void kernel_launch(void* const* d_in, const int* in_sizes, int n_in,
                              void* d_out, int out_size) {
    const float* x      = (const float*)d_in[0];
    const float* weight = (const float*)d_in[1];
    const float* pct    = (const float*)d_in[2];
    const float* ipct   = (const float*)d_in[3];
    float* out = (float*)d_out;

    // Resolve REAL device addresses (host-side &symbol is the shadow).
    float *p_fold, *p_Bf, *p_Bi, *p_xm, *p_xm2;
    cudaGetSymbolAddress((void**)&p_fold, g_fold4);
    cudaGetSymbolAddress((void**)&p_Bf,   g_Bf4);
    cudaGetSymbolAddress((void**)&p_Bi,   g_Bi4);
    cudaGetSymbolAddress((void**)&p_xm,   g_xm);
    cudaGetSymbolAddress((void**)&p_xm2,  g_xm2);

    kb_f3<<<(4 * KF * NBF + 255) / 256, 256>>>();
    kb_i3<<<(4 * KI * 192 + 255) / 256, 256>>>();
    {
        size_t n = (size_t)MM * HH * LL;
        kT_pct<<<(unsigned)((n + 255) / 256), 256>>>(pct);
        kT_ipct<<<(unsigned)((n + 255) / 256), 256>>>(ipct);
    }
    k_fold4<<<(NRr * 181 + 255) / 256, 256>>>(x, p_fold);

    // Forward: 4 parity GEMMs, 96-wide tiles (no pad waste)
    g1f96<<<dim3(NRr / 128, 4), 256>>>(p_fold, p_Bf, p_xm);

    k2_pct<<<dim3(12, 3, MM), 256>>>(weight);
    k3_ipct<<<dim3(12, 6, MM), 256>>>();

    // Inverse + fused combine (g_q4 scratch eliminated)
    g4c<<<dim3(NRr / 64, 3), 256>>>(p_xm2, p_Bi, out);

    if ((long long)out_size >= 2LL * NTOT) {
        cudaMemcpyAsync(out + NTOT, x, (size_t)NTOT * sizeof(float),
                        cudaMemcpyDeviceToDevice);
    }
}

// round 14
// speedup vs baseline: 1.4405x; 1.0403x over previous
#include <cuda_runtime.h>
#include <math.h>
#include <stdint.h>

// Problem dims
#define BB 2
#define CC 384
#define HH 360
#define WW 720
#define LL 180
#define MM 181
#define NF 362
#define NRr 276480               // BB*CC*HH
#define BCL 138240               // BB*CC*LL
#define NTOT 199065600

#define KF 192                   // padded fold length (181 -> 192)
#define NBF 96                   // padded mode dim per parity (91/90 -> 96)
#define KI 96                    // padded K per parity, inverse

typedef unsigned long long u64;

// ---------------- packed f32x2 helpers --------------------------------------
static __device__ __forceinline__ u64 dup2(float v) {
    u64 r;
    asm("mov.b64 %0, {%1, %1};" : "=l"(r) : "f"(v));
    return r;
}
static __device__ __forceinline__ void fma2(u64& d, u64 a, u64 b) {
    asm("fma.rn.f32x2 %0, %1, %2, %0;" : "+l"(d) : "l"(a), "l"(b));
}
static __device__ __forceinline__ float2 unpk(u64 v) {
    float2 f;
    asm("mov.b64 {%0, %1}, %2;" : "=f"(f.x), "=f"(f.y) : "l"(v));
    return f;
}

// ---------------- device globals (allocation-free; zero-init at load) ------
__device__ float g_fold4[4][(size_t)NRr * KF];   // EE, EO, OE, OO [row][k]
__device__ float g_Bf4[4][KF * NBF];             // fwd bases [z][k][n]
__device__ float g_Bi4[4][KI * 192];             // inv bases [z][k][j]
__device__ float g_xm[(size_t)384 * NRr];        // [plane][row], plane=4n+z
__device__ float g_cf[(size_t)NF * BCL];         // [2m+ri][bc*180+l]
__device__ float g_xm2[(size_t)384 * NRr];       // [plane][row]
__device__ float g_pctT[(size_t)MM * HH * LL];   // [m][h][l]
__device__ float g_ipctT[(size_t)MM * LL * HH];  // [m][l][h]

// ---------------- basis builders -------------------------------------------
__global__ void kb_f3() {
    int idx = blockIdx.x * 256 + threadIdx.x;
    if (idx >= 4 * KF * NBF) return;
    int z = idx / (KF * NBF);
    int r = (idx / NBF) % KF;
    int n = idx % NBF;
    float v = 0.f;
    double s, c;
    if (z == 0) {
        if (r <= 180 && n <= 90) { sincospi((double)(2 * n) * r / 360.0, &s, &c); v = (float)c; }
    } else if (z == 1) {
        if (r <= 179 && n <= 90) { sincospi((double)(2 * n) * (r + 1) / 360.0, &s, &c); v = (float)(-s); }
    } else if (z == 2) {
        if (r <= 180 && n <= 89) { sincospi((double)(2 * n + 1) * r / 360.0, &s, &c); v = (float)c; }
    } else {
        if (r <= 179 && n <= 89) { sincospi((double)(2 * n + 1) * (r + 1) / 360.0, &s, &c); v = (float)(-s); }
    }
    g_Bf4[0][idx] = v;
}

__global__ void kb_i3() {
    int idx = blockIdx.x * 256 + threadIdx.x;
    if (idx >= 4 * KI * 192) return;
    int z = idx / (KI * 192);
    int k = (idx / 192) % KI;
    int j = idx % 192;
    float v = 0.f;
    double s, c;
    if (j <= 180) {
        if (z < 2) {
            if (k <= 90) {
                int m = 2 * k;
                double sc = (m == 0 ? 1.0 : 2.0) / 720.0;
                sincospi((double)m * j / 360.0, &s, &c);
                v = (float)(sc * (z == 0 ? c : s));
            }
        } else {
            if (k <= 89) {
                int m = 2 * k + 1;
                sincospi((double)m * j / 360.0, &s, &c);
                v = (float)((2.0 / 720.0) * (z == 2 ? c : s));
            }
        }
    }
    g_Bi4[0][idx] = v;
}

// pctT[m][h][l] = pct[h][l][m]
__global__ void kT_pct(const float* __restrict__ pct) {
    size_t idx = (size_t)blockIdx.x * 256 + threadIdx.x;
    if (idx >= (size_t)MM * HH * LL) return;
    int l = (int)(idx % LL);
    size_t t = idx / LL;
    int h = (int)(t % HH);
    int m = (int)(t / HH);
    g_pctT[idx] = pct[((size_t)h * LL + l) * MM + m];
}
// ipctT[m][l][h] = ipct[h][l][m]
__global__ void kT_ipct(const float* __restrict__ ipct) {
    size_t idx = (size_t)blockIdx.x * 256 + threadIdx.x;
    if (idx >= (size_t)MM * LL * HH) return;
    int h = (int)(idx % HH);
    size_t t = idx / HH;
    int l = (int)(t % LL);
    int m = (int)(t / LL);
    g_ipctT[idx] = ipct[((size_t)h * LL + l) * MM + m];
}

// ---------------- double fold ----------------------------------------------
__global__ void k_fold4(const float* __restrict__ x, float* __restrict__ fold) {
    unsigned idx = blockIdx.x * 256u + threadIdx.x;
    if (idx >= (unsigned)NRr * 181u) return;
    int row = idx / 181;
    int w = idx - row * 181;
    const float* xr = x + (size_t)row * WW;
    float* EE = fold + (size_t)row * KF;
    float* EO = EE + (size_t)NRr * KF;
    float* OE = EO + (size_t)NRr * KF;
    float* OO = OE + (size_t)NRr * KF;
    if (w == 0) {
        EE[0] = xr[0] + xr[360];
        EO[0] = xr[0] - xr[360];
    } else if (w == 180) {
        float a = xr[180], b = xr[540];
        EE[180] = a + b;
        EO[180] = 0.f;
        OE[179] = 0.f;
        OO[179] = a - b;
    } else {
        float x1 = xr[w], x2 = xr[WW - w], x3 = xr[360 - w], x4 = xr[360 + w];
        EE[w] = x1 + x2 + x3 + x4;
        EO[w] = x1 + x2 - x3 - x4;
        OE[w - 1] = x1 - x2 - x3 + x4;
        OO[w - 1] = x1 - x2 + x3 - x4;
    }
}

// ---------------- forward GEMM: 128 rows x 96 modes, f32x2 ------------------
// xm[4n+z][row] = sum_k fold[Aidx(z)][row][k] * Bf[z][k][n]
__global__ __launch_bounds__(256) void g1f96(const float* __restrict__ fold,
                                             const float* __restrict__ Bf,
                                             float* __restrict__ xm) {
    __shared__ float As[16][132];
    __shared__ float Bs[16][96];
    int z = blockIdx.y;
    int Aidx = ((z & 1) << 1) | ((z >> 1) & 1);   // 0->EE,1->OE,2->EO,3->OO
    const float* A = fold + (size_t)Aidx * NRr * KF;
    const float* Bb = Bf + (size_t)z * (KF * NBF);
    int row0 = blockIdx.x * 128;
    int tid = threadIdx.x;
    int tx = tid & 31;   // row micro (x4)
    int ty = tid >> 5;   // col micro (x12 = 6 pairs)
    u64 acc[6][4];       // [col-pair][row]
#pragma unroll
    for (int j = 0; j < 6; j++)
#pragma unroll
        for (int i = 0; i < 4; i++) acc[j][i] = 0ull;

    int lr = tid >> 1, lkq = (tid & 1) * 8;
    const float* arow = A + (size_t)(row0 + lr) * KF + lkq;

    for (int k0 = 0; k0 < KF; k0 += 16) {
        {
            float4 v0 = *(const float4*)(arow + k0);
            float4 v1 = *(const float4*)(arow + k0 + 4);
            As[lkq + 0][lr] = v0.x; As[lkq + 1][lr] = v0.y;
            As[lkq + 2][lr] = v0.z; As[lkq + 3][lr] = v0.w;
            As[lkq + 4][lr] = v1.x; As[lkq + 5][lr] = v1.y;
            As[lkq + 6][lr] = v1.z; As[lkq + 7][lr] = v1.w;
        }
#pragma unroll
        for (int p = 0; p < 2; p++) {
            int i = tid + p * 256;
            if (i < 384) {
                int k = i / 24, c4 = (i % 24) * 4;
                *(float4*)&Bs[k][c4] = *(const float4*)(Bb + (size_t)(k0 + k) * NBF + c4);
            }
        }
        __syncthreads();
#pragma unroll
        for (int kk = 0; kk < 16; kk++) {
            float4 a4 = *(const float4*)&As[kk][tx * 4];
            const ulonglong2* bp = (const ulonglong2*)&Bs[kk][ty * 12];
            ulonglong2 b01 = bp[0];
            u64 b45 = ((const u64*)bp)[4];
            ulonglong2 b23 = bp[1];
            u64 ad[4] = {dup2(a4.x), dup2(a4.y), dup2(a4.z), dup2(a4.w)};
            u64 bv[6] = {b01.x, b01.y, b23.x, b23.y, b45, ((const u64*)bp)[5]};
#pragma unroll
            for (int j = 0; j < 6; j++)
#pragma unroll
                for (int i = 0; i < 4; i++) fma2(acc[j][i], ad[i], bv[j]);
        }
        __syncthreads();
    }
#pragma unroll
    for (int j = 0; j < 6; j++) {
        float2 u0 = unpk(acc[j][0]), u1 = unpk(acc[j][1]);
        float2 u2 = unpk(acc[j][2]), u3 = unpk(acc[j][3]);
        int n = ty * 12 + 2 * j;
        float4 e = make_float4(u0.x, u1.x, u2.x, u3.x);
        float4 o = make_float4(u0.y, u1.y, u2.y, u3.y);
        *(float4*)(xm + (size_t)(4 * n + z) * NRr + row0 + tx * 4) = e;
        *(float4*)(xm + (size_t)(4 * (n + 1) + z) * NRr + row0 + tx * 4) = o;
    }
}

// ---------------- K2 (f32x2, packed along bc) -------------------------------
__global__ __launch_bounds__(256) void k2_pct(const float* __restrict__ weight) {
    int m = blockIdx.z;
    int bc0 = blockIdx.x * 64;
    int l0 = blockIdx.y * 64;
    __shared__ float Ar[8][64], Ai[8][64], Ps[8][64];
    int tid = threadIdx.x;
    int tx = tid & 15;
    int ty = tid >> 4;
    u64 accR[2][4], accI[2][4];   // [bc-pair][l]
#pragma unroll
    for (int i = 0; i < 2; i++)
#pragma unroll
        for (int j = 0; j < 4; j++) { accR[i][j] = 0ull; accI[i][j] = 0ull; }

    const float* xr = g_xm + (size_t)(2 * m) * NRr;
    const float* xi = xr + NRr;

    for (int h0 = 0; h0 < HH; h0 += 8) {
        {
            int r = tid >> 2;
            int k2 = (tid & 3) * 2;
            size_t base = (size_t)(bc0 + r) * HH + h0 + k2;
            float2 vr = *(const float2*)(xr + base);
            Ar[k2][r] = vr.x; Ar[k2 + 1][r] = vr.y;
            float2 vi = *(const float2*)(xi + base);
            Ai[k2][r] = vi.x; Ai[k2 + 1][r] = vi.y;
        }
        {
            int k = tid >> 5;
            int c2 = (tid & 31) * 2;
            const float* Pm = g_pctT + ((size_t)m * HH + h0 + k) * LL;
#pragma unroll
            for (int j = 0; j < 2; j++) {
                int l = l0 + c2 + j;
                Ps[k][c2 + j] = (l < LL) ? Pm[l] : 0.f;
            }
        }
        __syncthreads();
#pragma unroll
        for (int k = 0; k < 8; k++) {
            ulonglong2 ar2 = *(const ulonglong2*)&Ar[k][ty * 4];
            ulonglong2 ai2 = *(const ulonglong2*)&Ai[k][ty * 4];
            float4 p4 = *(const float4*)&Ps[k][tx * 4];
            u64 pb[4] = {dup2(p4.x), dup2(p4.y), dup2(p4.z), dup2(p4.w)};
            u64 arv[2] = {ar2.x, ar2.y};
            u64 aiv[2] = {ai2.x, ai2.y};
#pragma unroll
            for (int i = 0; i < 2; i++)
#pragma unroll
                for (int j = 0; j < 4; j++) {
                    fma2(accR[i][j], arv[i], pb[j]);
                    fma2(accI[i][j], aiv[i], pb[j]);
                }
        }
        __syncthreads();
    }
    float* cr = g_cf + (size_t)(2 * m) * BCL;
    float* ci = cr + BCL;
#pragma unroll
    for (int i2 = 0; i2 < 2; i2++) {
#pragma unroll
        for (int j = 0; j < 4; j++) {
            float2 vR = unpk(accR[i2][j]);
            float2 vI = unpk(accI[i2][j]);
            int l = l0 + tx * 4 + j;
            if (l >= LL) continue;
#pragma unroll
            for (int lane = 0; lane < 2; lane++) {
                int bc = bc0 + ty * 4 + 2 * i2 + lane;
                int c = bc % CC;
                float aR = lane ? vR.y : vR.x;
                float aI = lane ? vI.y : vI.x;
                float2 wv = *(const float2*)(weight + (((size_t)c * LL + l) * MM + m) * 2);
                size_t o = (size_t)bc * LL + l;
                cr[o] = aR * wv.x - aI * wv.y;
                ci[o] = aR * wv.y + aI * wv.x;
            }
        }
    }
}

// ---------------- K3 (f32x2, packed along bc) -------------------------------
__global__ __launch_bounds__(256) void k3_ipct() {
    int m = blockIdx.z;
    int bc0 = blockIdx.x * 64;
    int h0 = blockIdx.y * 64;
    __shared__ float Ar[8][64], Ai[8][64], Qs[8][64];
    int tid = threadIdx.x;
    int tx = tid & 15;
    int ty = tid >> 4;
    u64 accR[2][4], accI[2][4];
#pragma unroll
    for (int i = 0; i < 2; i++)
#pragma unroll
        for (int j = 0; j < 4; j++) { accR[i][j] = 0ull; accI[i][j] = 0ull; }

    const float* cr = g_cf + (size_t)(2 * m) * BCL;
    const float* ci = cr + BCL;

    for (int l0 = 0; l0 < LL; l0 += 8) {
        {
            int r = tid >> 2;
            int k2 = (tid & 3) * 2;
            int l = l0 + k2;
            size_t base = (size_t)(bc0 + r) * LL + l;
            Ar[k2][r]     = (l < LL)     ? cr[base]     : 0.f;
            Ar[k2 + 1][r] = (l + 1 < LL) ? cr[base + 1] : 0.f;
            Ai[k2][r]     = (l < LL)     ? ci[base]     : 0.f;
            Ai[k2 + 1][r] = (l + 1 < LL) ? ci[base + 1] : 0.f;
        }
        {
            int k = tid >> 5;
            int c2 = (tid & 31) * 2;
            int l = l0 + k;
            const float* Qm = g_ipctT + ((size_t)m * LL + l) * HH;
#pragma unroll
            for (int j = 0; j < 2; j++) {
                int h = h0 + c2 + j;
                Qs[k][c2 + j] = (l < LL && h < HH) ? Qm[h] : 0.f;
            }
        }
        __syncthreads();
#pragma unroll
        for (int k = 0; k < 8; k++) {
            ulonglong2 ar2 = *(const ulonglong2*)&Ar[k][ty * 4];
            ulonglong2 ai2 = *(const ulonglong2*)&Ai[k][ty * 4];
            float4 q4 = *(const float4*)&Qs[k][tx * 4];
            u64 qb[4] = {dup2(q4.x), dup2(q4.y), dup2(q4.z), dup2(q4.w)};
            u64 arv[2] = {ar2.x, ar2.y};
            u64 aiv[2] = {ai2.x, ai2.y};
#pragma unroll
            for (int i = 0; i < 2; i++)
#pragma unroll
                for (int j = 0; j < 4; j++) {
                    fma2(accR[i][j], arv[i], qb[j]);
                    fma2(accI[i][j], aiv[i], qb[j]);
                }
        }
        __syncthreads();
    }
    float* orp = g_xm2 + (size_t)(2 * m) * NRr;
    float* oip = orp + NRr;
#pragma unroll
    for (int i2 = 0; i2 < 2; i2++) {
#pragma unroll
        for (int j = 0; j < 4; j++) {
            float2 vR = unpk(accR[i2][j]);
            float2 vI = unpk(accI[i2][j]);
            int h = h0 + tx * 4 + j;
            if (h >= HH) continue;
#pragma unroll
            for (int lane = 0; lane < 2; lane++) {
                int bc = bc0 + ty * 4 + 2 * i2 + lane;
                size_t o = (size_t)bc * HH + h;
                orp[o] = lane ? vR.y : vR.x;
                oip[o] = lane ? vI.y : vI.x;
            }
        }
    }
}

// ---------------- inverse GEMM + fused 4-quadrant combine (f32x2) ----------
__global__ __launch_bounds__(256) void g4c(const float* __restrict__ xm2,
                                           const float* __restrict__ Bi,
                                           float* __restrict__ out) {
    __shared__ float As[4][16][68];
    __shared__ float Bs[4][16][68];
    int row0 = blockIdx.x * 64;
    int j0 = blockIdx.y * 64;
    int tid = threadIdx.x;
    int tx = tid & 15;   // j micro (x4 = 2 pairs)
    int ty = tid >> 4;   // row micro (x4)
    u64 acc[4][4][2];    // [z][row i][j-pair]
#pragma unroll
    for (int z = 0; z < 4; z++)
#pragma unroll
        for (int i = 0; i < 4; i++)
#pragma unroll
            for (int j = 0; j < 2; j++) acc[z][i][j] = 0ull;

    for (int k0 = 0; k0 < KI; k0 += 16) {
#pragma unroll
        for (int p = 0; p < 4; p++) {
            int i = tid + p * 256;
            int z = i >> 8, k = (i >> 4) & 15, c4 = (i & 15) * 4;
            *(float4*)&As[z][k][c4] =
                *(const float4*)(xm2 + (size_t)(4 * (k0 + k) + z) * NRr + row0 + c4);
            *(float4*)&Bs[z][k][c4] =
                *(const float4*)(Bi + (size_t)z * (KI * 192) + (size_t)(k0 + k) * 192 + j0 + c4);
        }
        __syncthreads();
#pragma unroll
        for (int kk = 0; kk < 16; kk++) {
#pragma unroll
            for (int z = 0; z < 4; z++) {
                float4 a4 = *(const float4*)&As[z][kk][ty * 4];
                ulonglong2 b2 = *(const ulonglong2*)&Bs[z][kk][tx * 4];
                u64 ad[4] = {dup2(a4.x), dup2(a4.y), dup2(a4.z), dup2(a4.w)};
                u64 bv[2] = {b2.x, b2.y};
#pragma unroll
                for (int i = 0; i < 4; i++)
#pragma unroll
                    for (int j = 0; j < 2; j++) fma2(acc[z][i][j], ad[i], bv[j]);
            }
        }
        __syncthreads();
    }
    // fused combine epilogue
#pragma unroll
    for (int i = 0; i < 4; i++) {
        int row = row0 + ty * 4 + i;
        float* o = out + (size_t)row * WW;
#pragma unroll
        for (int jp = 0; jp < 2; jp++) {
            float2 v0 = unpk(acc[0][i][jp]);
            float2 v1 = unpk(acc[1][i][jp]);
            float2 v2 = unpk(acc[2][i][jp]);
            float2 v3 = unpk(acc[3][i][jp]);
#pragma unroll
            for (int lane = 0; lane < 2; lane++) {
                int jj = j0 + tx * 4 + 2 * jp + lane;
                if (jj > 180) continue;
                float q0 = lane ? v0.y : v0.x;
                float q1 = lane ? v1.y : v1.x;
                float q2 = lane ? v2.y : v2.x;
                float q3 = lane ? v3.y : v3.x;
                float a = q0 + q2, b = q1 + q3, c = q0 - q2, d = q1 - q3;
                o[jj] = a - b;
                o[360 - jj] = c + d;
                if (jj >= 1) {
                    o[WW - jj] = a + b;
                    o[360 + jj] = c - d;
                }
            }
        }
    }
}

// ---------------------------------------------------------------------------
extern "C" void kernel_launch(void* const* d_in, const int* in_sizes, int n_in,
                              void* d_out, int out_size) {
    const float* x      = (const float*)d_in[0];
    const float* weight = (const float*)d_in[1];
    const float* pct    = (const float*)d_in[2];
    const float* ipct   = (const float*)d_in[3];
    float* out = (float*)d_out;

    // Resolve REAL device addresses (host-side &symbol is the shadow).
    float *p_fold, *p_Bf, *p_Bi, *p_xm, *p_xm2;
    cudaGetSymbolAddress((void**)&p_fold, g_fold4);
    cudaGetSymbolAddress((void**)&p_Bf,   g_Bf4);
    cudaGetSymbolAddress((void**)&p_Bi,   g_Bi4);
    cudaGetSymbolAddress((void**)&p_xm,   g_xm);
    cudaGetSymbolAddress((void**)&p_xm2,  g_xm2);

    kb_f3<<<(4 * KF * NBF + 255) / 256, 256>>>();
    kb_i3<<<(4 * KI * 192 + 255) / 256, 256>>>();
    {
        size_t n = (size_t)MM * HH * LL;
        kT_pct<<<(unsigned)((n + 255) / 256), 256>>>(pct);
        kT_ipct<<<(unsigned)((n + 255) / 256), 256>>>(ipct);
    }
    k_fold4<<<(NRr * 181 + 255) / 256, 256>>>(x, p_fold);

    g1f96<<<dim3(NRr / 128, 4), 256>>>(p_fold, p_Bf, p_xm);

    k2_pct<<<dim3(12, 3, MM), 256>>>(weight);
    k3_ipct<<<dim3(12, 6, MM), 256>>>();

    g4c<<<dim3(NRr / 64, 3), 256>>>(p_xm2, p_Bi, out);

    if ((long long)out_size >= 2LL * NTOT) {
        cudaMemcpyAsync(out + NTOT, x, (size_t)NTOT * sizeof(float),
                        cudaMemcpyDeviceToDevice);
    }
}